// round 2
// baseline (speedup 1.0000x reference)
#include <cuda_runtime.h>
#include <math.h>
#include <stdint.h>

#define BSZ 8
#define LSEQ 2048
#define DM 512
#define NS 64
#define EMB 512

// Scratch (allocation-free rule: __device__ globals)
__device__ float g_xn[BSZ * LSEQ * DM];    // LayerNorm output, (B,L,d)
__device__ float g_y2[BSZ * LSEQ * DM];    // post-conv, post-FiLM, (B,L,d)
__device__ float g_film[BSZ * 2 * DM];     // FiLM scale/shift

// ---------------------------------------------------------------------------
// f32x2 packed-math helpers (Blackwell FFMA2 path)
// ---------------------------------------------------------------------------
__device__ __forceinline__ unsigned long long pk2(float a, float b) {
    unsigned long long r;
    asm("mov.b64 %0, {%1, %2};" : "=l"(r) : "f"(a), "f"(b));
    return r;
}
__device__ __forceinline__ float2 upk2(unsigned long long v) {
    float2 f;
    asm("mov.b64 {%0, %1}, %2;" : "=f"(f.x), "=f"(f.y) : "l"(v));
    return f;
}
__device__ __forceinline__ unsigned long long fma2(unsigned long long a,
                                                   unsigned long long b,
                                                   unsigned long long c) {
    unsigned long long d;
    asm("fma.rn.f32x2 %0, %1, %2, %3;" : "=l"(d) : "l"(a), "l"(b), "l"(c));
    return d;
}
__device__ __forceinline__ unsigned long long mul2(unsigned long long a,
                                                   unsigned long long b) {
    unsigned long long d;
    asm("mul.rn.f32x2 %0, %1, %2;" : "=l"(d) : "l"(a), "l"(b));
    return d;
}

// tf32 round (rna) — returns fp32 bit pattern with truncated mantissa
__device__ __forceinline__ uint32_t f2tf(float x) {
    uint32_t r;
    asm("cvt.rna.tf32.f32 %0, %1;" : "=r"(r) : "f"(x));
    return r;
}

// ---------------------------------------------------------------------------
// Kernel 1: LayerNorm over last dim (512). One block per (b,l) row.
// ---------------------------------------------------------------------------
__global__ void ln_kernel(const float* __restrict__ x,
                          const float* __restrict__ gamma,
                          const float* __restrict__ beta) {
    const int row = blockIdx.x;
    const int t = threadIdx.x;
    const float4* xr = (const float4*)(x + (size_t)row * DM);
    float4 v = xr[t];
    float s  = v.x + v.y + v.z + v.w;
    float ss = v.x * v.x + v.y * v.y + v.z * v.z + v.w * v.w;

    __shared__ float sh[8];
    #pragma unroll
    for (int o = 16; o; o >>= 1) {
        s  += __shfl_xor_sync(0xffffffffu, s, o);
        ss += __shfl_xor_sync(0xffffffffu, ss, o);
    }
    int w = t >> 5;
    if ((t & 31) == 0) { sh[w] = s; sh[4 + w] = ss; }
    __syncthreads();
    float S  = sh[0] + sh[1] + sh[2] + sh[3];
    float SS = sh[4] + sh[5] + sh[6] + sh[7];

    const float inv = 1.0f / (float)DM;
    float mu = S * inv;
    float var = SS * inv - mu * mu;
    float rs = rsqrtf(var + 1e-5f);

    float4 g4 = ((const float4*)gamma)[t];
    float4 b4 = ((const float4*)beta)[t];
    float4 o4;
    o4.x = (v.x - mu) * rs * g4.x + b4.x;
    o4.y = (v.y - mu) * rs * g4.y + b4.y;
    o4.z = (v.z - mu) * rs * g4.z + b4.z;
    o4.w = (v.w - mu) * rs * g4.w + b4.w;
    ((float4*)(g_xn + (size_t)row * DM))[t] = o4;
}

// ---------------------------------------------------------------------------
// Kernel 2: FiLM params
// ---------------------------------------------------------------------------
__global__ void film_kernel(const float* __restrict__ emb,
                            const float* __restrict__ Wf,
                            const float* __restrict__ bf) {
    __shared__ float se[EMB];
    const int b = blockIdx.x;
    for (int i = threadIdx.x; i < EMB; i += blockDim.x) {
        float e = emb[b * EMB + i];
        se[i] = e / (1.0f + expf(-e));
    }
    __syncthreads();
    for (int j = threadIdx.x; j < 2 * DM; j += blockDim.x) {
        const float4* wr = (const float4*)(Wf + (size_t)j * EMB);
        const float4* sr = (const float4*)se;
        float acc = bf[j];
        #pragma unroll 4
        for (int q = 0; q < EMB / 4; q++) {
            float4 w = wr[q], sv = sr[q];
            acc += w.x * sv.x + w.y * sv.y + w.z * sv.z + w.w * sv.w;
        }
        g_film[b * 2 * DM + j] = acc;
    }
}

// ---------------------------------------------------------------------------
// Kernel 3: S4D complex scan + D-skip + FiLM, f32x2 packed.
// 8 lanes per d, each lane holds 4 complex-state PAIRS (8 of 64 states).
// Block = 128 threads = 16 consecutive d of one batch.
// ---------------------------------------------------------------------------
__global__ void scan_kernel(const float* __restrict__ A_real,
                            const float* __restrict__ A_imag,
                            const float* __restrict__ Cp,
                            const float* __restrict__ log_dt,
                            const float* __restrict__ B_ssm,
                            const float* __restrict__ D_skip) {
    const int t = threadIdx.x;        // 0..127
    const int myd = t >> 3;           // 0..15 (which d in block)
    const int g = t & 7;              // lane within d-group
    const int gid = blockIdx.x * 16 + myd;
    const int b = gid >> 9;
    const int d = gid & 511;
    const int d0 = (blockIdx.x * 16) & 511;

    const float dt = expf(log_dt[d]);
    unsigned long long Abr[4], Abi[4], nAbi[4], Ccr[4], nCci[4], s_r[4], s_i[4];
    #pragma unroll
    for (int p = 0; p < 4; p++) {
        float abr[2], abi[2], ccr[2], cci[2];
        #pragma unroll
        for (int j = 0; j < 2; j++) {
            int n = g * 8 + p * 2 + j;
            float ar = dt * A_real[d * NS + n];
            float ai = dt * A_imag[d * NS + n];
            float er = expf(ar), sb, cb;
            sincosf(ai, &sb, &cb);
            abr[j] = er * cb;
            abi[j] = er * sb;
            float bs = B_ssm[d * NS + n];
            ccr[j] = Cp[(d * NS + n) * 2 + 0] * bs;
            cci[j] = Cp[(d * NS + n) * 2 + 1] * bs;
        }
        Abr[p]  = pk2(abr[0], abr[1]);
        Abi[p]  = pk2(abi[0], abi[1]);
        nAbi[p] = pk2(-abi[0], -abi[1]);
        Ccr[p]  = pk2(ccr[0], ccr[1]);
        nCci[p] = pk2(-cci[0], -cci[1]);
        s_r[p] = 0ull; s_i[p] = 0ull;
    }
    const float dsk = D_skip[d];
    const float mult  = 1.0f + g_film[b * 2 * DM + d];
    const float shift = g_film[b * 2 * DM + DM + d];

    __shared__ float sx[2][64][16];
    const float* xbase = g_xn + (size_t)b * LSEQ * DM + d0;
    float* ybase = g_y2 + (size_t)b * LSEQ * DM + d;

    // load mapping: 64 l x 4 float4 each = 256 float4, 2 per thread
    const int l0 = t >> 2, quad0 = t & 3;
    const int l1 = (t + 128) >> 2, quad1 = t & 3;

    *(float4*)&sx[0][l0][quad0 * 4] = *(const float4*)(xbase + (size_t)l0 * DM + quad0 * 4);
    *(float4*)&sx[0][l1][quad1 * 4] = *(const float4*)(xbase + (size_t)l1 * DM + quad1 * 4);
    __syncthreads();

    for (int chunk = 0; chunk < LSEQ / 64; chunk++) {
        const int cur = chunk & 1;
        float4 nv0, nv1;
        const bool more = (chunk + 1 < LSEQ / 64);
        if (more) {
            const float* nb = xbase + (size_t)(chunk + 1) * 64 * DM;
            nv0 = *(const float4*)(nb + (size_t)l0 * DM + quad0 * 4);
            nv1 = *(const float4*)(nb + (size_t)l1 * DM + quad1 * 4);
        }
        #pragma unroll 4
        for (int i = 0; i < 64; i++) {
            float xv = sx[cur][i][myd];
            unsigned long long x2 = pk2(xv, xv);
            unsigned long long acc = 0ull;
            #pragma unroll
            for (int p = 0; p < 4; p++) {
                unsigned long long t1 = fma2(nAbi[p], s_i[p], x2);
                unsigned long long nr = fma2(Abr[p], s_r[p], t1);
                unsigned long long u  = mul2(Abi[p], s_r[p]);
                unsigned long long ni = fma2(Abr[p], s_i[p], u);
                s_r[p] = nr; s_i[p] = ni;
                acc = fma2(Ccr[p], nr, acc);
                acc = fma2(nCci[p], ni, acc);
            }
            float2 ac = upk2(acc);
            float tsum = ac.x + ac.y;
            tsum += __shfl_xor_sync(0xffffffffu, tsum, 4);
            tsum += __shfl_xor_sync(0xffffffffu, tsum, 2);
            tsum += __shfl_xor_sync(0xffffffffu, tsum, 1);
            if (g == 0) {
                float o = dt * tsum + dsk * xv;
                ybase[(size_t)(chunk * 64 + i) * DM] = o * mult + shift;
            }
        }
        if (more) {
            *(float4*)&sx[cur ^ 1][l0][quad0 * 4] = nv0;
            *(float4*)&sx[cur ^ 1][l1][quad1 * 4] = nv1;
        }
        __syncthreads();
    }
}

// ---------------------------------------------------------------------------
// Kernel 4: out_proj GEMM via 3xTF32 mma.sync.m16n8k8 + GLU + residual.
// Block tile: 128 m x 64 a-cols (+ paired 64 g-cols). BK=16.
// 8 warps: 4 m-warps x 2 n-warps; warp tile 32m x 32n (a and g both).
// ---------------------------------------------------------------------------
#define TBM 128
#define TBK 16
#define TBKP 20   // padded k stride (conflict-free fragment loads)

__device__ __forceinline__ void mma_tf32(float d[4], const uint32_t a[4],
                                         const uint32_t b0, const uint32_t b1) {
    asm volatile(
        "mma.sync.aligned.m16n8k8.row.col.f32.tf32.tf32.f32 "
        "{%0,%1,%2,%3}, {%4,%5,%6,%7}, {%8,%9}, {%0,%1,%2,%3};\n"
        : "+f"(d[0]), "+f"(d[1]), "+f"(d[2]), "+f"(d[3])
        : "r"(a[0]), "r"(a[1]), "r"(a[2]), "r"(a[3]), "r"(b0), "r"(b1));
}

__global__ void __launch_bounds__(256, 1)
gemm_glu_tc(const float* __restrict__ W,
            const float* __restrict__ bo,
            const float* __restrict__ resid,
            float* __restrict__ out) {
    __shared__ float Ah[TBM][TBKP];
    __shared__ float Al[TBM][TBKP];
    __shared__ float Bh[TBM][TBKP];   // rows 0..63 = a-cols, 64..127 = g-cols
    __shared__ float Bl[TBM][TBKP];

    const int tid = threadIdx.x;
    const int m0 = blockIdx.x * TBM;
    const int c0 = blockIdx.y * 64;
    const int warp = tid >> 5, lane = tid & 31;
    const int wm = warp & 3, wn = warp >> 2;
    const int grp = lane >> 2, tig = lane & 3;

    float da[2][4][4];
    float dg[2][4][4];
    #pragma unroll
    for (int mt = 0; mt < 2; mt++)
        #pragma unroll
        for (int nt = 0; nt < 4; nt++)
            #pragma unroll
            for (int r = 0; r < 4; r++) { da[mt][nt][r] = 0.0f; dg[mt][nt][r] = 0.0f; }

    // load indices (2 float4 per thread per tile, for both A and B)
    const int qm0 = tid >> 2,            qk0 = tid & 3;
    const int qm1 = (tid + 256) >> 2,    qk1 = tid & 3;

    for (int kt = 0; kt < DM; kt += TBK) {
        // ---- A tile: g_y2[m0+m][kt + k], 128 x 16 ----
        {
            float4 v0 = *(const float4*)(g_y2 + (size_t)(m0 + qm0) * DM + kt + qk0 * 4);
            float4 v1 = *(const float4*)(g_y2 + (size_t)(m0 + qm1) * DM + kt + qk1 * 4);
            float e0[4] = {v0.x, v0.y, v0.z, v0.w};
            float e1[4] = {v1.x, v1.y, v1.z, v1.w};
            #pragma unroll
            for (int j = 0; j < 4; j++) {
                uint32_t h = f2tf(e0[j]);
                float hf = __uint_as_float(h);
                Ah[qm0][qk0 * 4 + j] = hf;
                Al[qm0][qk0 * 4 + j] = __uint_as_float(f2tf(e0[j] - hf));
                uint32_t h1 = f2tf(e1[j]);
                float hf1 = __uint_as_float(h1);
                Ah[qm1][qk1 * 4 + j] = hf1;
                Al[qm1][qk1 * 4 + j] = __uint_as_float(f2tf(e1[j] - hf1));
            }
        }
        // ---- B tile: W rows (a: c0+r, g: 512+c0+r), 128 x 16 ----
        {
            int r0 = qm0, r1 = qm1;
            int row0 = (r0 < 64) ? (c0 + r0) : (DM + c0 + r0 - 64);
            int row1 = (r1 < 64) ? (c0 + r1) : (DM + c0 + r1 - 64);
            float4 v0 = *(const float4*)(W + (size_t)row0 * DM + kt + qk0 * 4);
            float4 v1 = *(const float4*)(W + (size_t)row1 * DM + kt + qk1 * 4);
            float e0[4] = {v0.x, v0.y, v0.z, v0.w};
            float e1[4] = {v1.x, v1.y, v1.z, v1.w};
            #pragma unroll
            for (int j = 0; j < 4; j++) {
                uint32_t h = f2tf(e0[j]);
                float hf = __uint_as_float(h);
                Bh[r0][qk0 * 4 + j] = hf;
                Bl[r0][qk0 * 4 + j] = __uint_as_float(f2tf(e0[j] - hf));
                uint32_t h1 = f2tf(e1[j]);
                float hf1 = __uint_as_float(h1);
                Bh[r1][qk1 * 4 + j] = hf1;
                Bl[r1][qk1 * 4 + j] = __uint_as_float(f2tf(e1[j] - hf1));
            }
        }
        __syncthreads();

        #pragma unroll
        for (int kk = 0; kk < 2; kk++) {
            const int kb = kk * 8;
            // A fragments
            uint32_t ah[2][4], al[2][4];
            #pragma unroll
            for (int mt = 0; mt < 2; mt++) {
                int m = wm * 32 + mt * 16;
                ah[mt][0] = __float_as_uint(Ah[m + grp][kb + tig]);
                ah[mt][1] = __float_as_uint(Ah[m + grp + 8][kb + tig]);
                ah[mt][2] = __float_as_uint(Ah[m + grp][kb + tig + 4]);
                ah[mt][3] = __float_as_uint(Ah[m + grp + 8][kb + tig + 4]);
                al[mt][0] = __float_as_uint(Al[m + grp][kb + tig]);
                al[mt][1] = __float_as_uint(Al[m + grp + 8][kb + tig]);
                al[mt][2] = __float_as_uint(Al[m + grp][kb + tig + 4]);
                al[mt][3] = __float_as_uint(Al[m + grp + 8][kb + tig + 4]);
            }
            // B fragments (a and g halves)
            uint32_t bha[4][2], bla[4][2], bhg[4][2], blg[4][2];
            #pragma unroll
            for (int nt = 0; nt < 4; nt++) {
                int na = wn * 32 + nt * 8 + grp;   // 0..63
                int ng = 64 + na;
                bha[nt][0] = __float_as_uint(Bh[na][kb + tig]);
                bha[nt][1] = __float_as_uint(Bh[na][kb + tig + 4]);
                bla[nt][0] = __float_as_uint(Bl[na][kb + tig]);
                bla[nt][1] = __float_as_uint(Bl[na][kb + tig + 4]);
                bhg[nt][0] = __float_as_uint(Bh[ng][kb + tig]);
                bhg[nt][1] = __float_as_uint(Bh[ng][kb + tig + 4]);
                blg[nt][0] = __float_as_uint(Bl[ng][kb + tig]);
                blg[nt][1] = __float_as_uint(Bl[ng][kb + tig + 4]);
            }
            #pragma unroll
            for (int mt = 0; mt < 2; mt++) {
                #pragma unroll
                for (int nt = 0; nt < 4; nt++) {
                    mma_tf32(da[mt][nt], ah[mt], bha[nt][0], bha[nt][1]);
                    mma_tf32(da[mt][nt], ah[mt], bla[nt][0], bla[nt][1]);
                    mma_tf32(da[mt][nt], al[mt], bha[nt][0], bha[nt][1]);
                    mma_tf32(dg[mt][nt], ah[mt], bhg[nt][0], bhg[nt][1]);
                    mma_tf32(dg[mt][nt], ah[mt], blg[nt][0], blg[nt][1]);
                    mma_tf32(dg[mt][nt], al[mt], bhg[nt][0], bhg[nt][1]);
                }
            }
        }
        __syncthreads();
    }

    // epilogue: a*sigmoid(g) + residual
    #pragma unroll
    for (int mt = 0; mt < 2; mt++) {
        #pragma unroll
        for (int nt = 0; nt < 4; nt++) {
            int col = c0 + wn * 32 + nt * 8 + tig * 2;
            float ba0 = bo[col], ba1 = bo[col + 1];
            float bg0 = bo[DM + col], bg1 = bo[DM + col + 1];
            #pragma unroll
            for (int half = 0; half < 2; half++) {
                int r = m0 + wm * 32 + mt * 16 + grp + half * 8;
                float a0 = da[mt][nt][half * 2 + 0] + ba0;
                float a1 = da[mt][nt][half * 2 + 1] + ba1;
                float g0 = dg[mt][nt][half * 2 + 0] + bg0;
                float g1 = dg[mt][nt][half * 2 + 1] + bg1;
                float2 res = *(const float2*)(resid + (size_t)r * DM + col);
                float2 o;
                o.x = res.x + a0 * (1.0f / (1.0f + expf(-g0)));
                o.y = res.y + a1 * (1.0f / (1.0f + expf(-g1)));
                *(float2*)(out + (size_t)r * DM + col) = o;
            }
        }
    }
}

// ---------------------------------------------------------------------------
extern "C" void kernel_launch(void* const* d_in, const int* in_sizes, int n_in,
                              void* d_out, int out_size) {
    const float* x      = (const float*)d_in[0];
    const float* emb    = (const float*)d_in[1];
    const float* A_real = (const float*)d_in[2];
    const float* A_imag = (const float*)d_in[3];
    const float* C      = (const float*)d_in[4];
    const float* log_dt = (const float*)d_in[5];
    const float* B_ssm  = (const float*)d_in[6];
    const float* D_skip = (const float*)d_in[7];
    const float* ln_g   = (const float*)d_in[8];
    const float* ln_b   = (const float*)d_in[9];
    const float* W_out  = (const float*)d_in[10];
    const float* b_out  = (const float*)d_in[11];
    const float* W_film = (const float*)d_in[12];
    const float* b_film = (const float*)d_in[13];
    float* out = (float*)d_out;

    ln_kernel<<<BSZ * LSEQ, 128>>>(x, ln_g, ln_b);
    film_kernel<<<BSZ, 256>>>(emb, W_film, b_film);
    scan_kernel<<<(BSZ * DM) / 16, 128>>>(A_real, A_imag, C, log_dt, B_ssm, D_skip);
    gemm_glu_tc<<<dim3((BSZ * LSEQ) / TBM, DM / 64), 256>>>(W_out, b_out, x, out);
}

// round 3
// speedup vs baseline: 1.4598x; 1.4598x over previous
#include <cuda_runtime.h>
#include <cuda_bf16.h>
#include <math.h>
#include <stdint.h>

#define BSZ 8
#define LSEQ 2048
#define DM 512
#define NS 64
#define EMB 512

// Scratch (allocation-free rule: __device__ globals)
__device__ float g_xn[BSZ * LSEQ * DM];            // LayerNorm output
__device__ __nv_bfloat16 g_y2h[BSZ * LSEQ * DM];   // y2 hi split
__device__ __nv_bfloat16 g_y2l[BSZ * LSEQ * DM];   // y2 lo split
__device__ __nv_bfloat16 g_Wh[2 * DM * DM];        // W hi split
__device__ __nv_bfloat16 g_Wl[2 * DM * DM];        // W lo split
__device__ float g_film[BSZ * 2 * DM];

// ---------------------------------------------------------------------------
// f32x2 packed-math helpers
// ---------------------------------------------------------------------------
__device__ __forceinline__ unsigned long long pk2(float a, float b) {
    unsigned long long r;
    asm("mov.b64 %0, {%1, %2};" : "=l"(r) : "f"(a), "f"(b));
    return r;
}
__device__ __forceinline__ float2 upk2(unsigned long long v) {
    float2 f;
    asm("mov.b64 {%0, %1}, %2;" : "=f"(f.x), "=f"(f.y) : "l"(v));
    return f;
}
__device__ __forceinline__ unsigned long long fma2(unsigned long long a,
                                                   unsigned long long b,
                                                   unsigned long long c) {
    unsigned long long d;
    asm("fma.rn.f32x2 %0, %1, %2, %3;" : "=l"(d) : "l"(a), "l"(b), "l"(c));
    return d;
}
__device__ __forceinline__ unsigned long long mul2(unsigned long long a,
                                                   unsigned long long b) {
    unsigned long long d;
    asm("mul.rn.f32x2 %0, %1, %2;" : "=l"(d) : "l"(a), "l"(b));
    return d;
}

__device__ __forceinline__ void cpa16(uint32_t dst, const void* src) {
    asm volatile("cp.async.cg.shared.global [%0], [%1], 16;" :: "r"(dst), "l"(src));
}

// ---------------------------------------------------------------------------
// Kernel 1: LayerNorm
// ---------------------------------------------------------------------------
__global__ void ln_kernel(const float* __restrict__ x,
                          const float* __restrict__ gamma,
                          const float* __restrict__ beta) {
    const int row = blockIdx.x;
    const int t = threadIdx.x;
    const float4* xr = (const float4*)(x + (size_t)row * DM);
    float4 v = xr[t];
    float s  = v.x + v.y + v.z + v.w;
    float ss = v.x * v.x + v.y * v.y + v.z * v.z + v.w * v.w;

    __shared__ float sh[8];
    #pragma unroll
    for (int o = 16; o; o >>= 1) {
        s  += __shfl_xor_sync(0xffffffffu, s, o);
        ss += __shfl_xor_sync(0xffffffffu, ss, o);
    }
    int w = t >> 5;
    if ((t & 31) == 0) { sh[w] = s; sh[4 + w] = ss; }
    __syncthreads();
    float S  = sh[0] + sh[1] + sh[2] + sh[3];
    float SS = sh[4] + sh[5] + sh[6] + sh[7];

    const float inv = 1.0f / (float)DM;
    float mu = S * inv;
    float var = SS * inv - mu * mu;
    float rs = rsqrtf(var + 1e-5f);

    float4 g4 = ((const float4*)gamma)[t];
    float4 b4 = ((const float4*)beta)[t];
    float4 o4;
    o4.x = (v.x - mu) * rs * g4.x + b4.x;
    o4.y = (v.y - mu) * rs * g4.y + b4.y;
    o4.z = (v.z - mu) * rs * g4.z + b4.z;
    o4.w = (v.w - mu) * rs * g4.w + b4.w;
    ((float4*)(g_xn + (size_t)row * DM))[t] = o4;
}

// ---------------------------------------------------------------------------
// Kernel 2: FiLM params
// ---------------------------------------------------------------------------
__global__ void film_kernel(const float* __restrict__ emb,
                            const float* __restrict__ Wf,
                            const float* __restrict__ bf) {
    __shared__ float se[EMB];
    const int b = blockIdx.x;
    for (int i = threadIdx.x; i < EMB; i += blockDim.x) {
        float e = emb[b * EMB + i];
        se[i] = e / (1.0f + expf(-e));
    }
    __syncthreads();
    for (int j = threadIdx.x; j < 2 * DM; j += blockDim.x) {
        const float4* wr = (const float4*)(Wf + (size_t)j * EMB);
        const float4* sr = (const float4*)se;
        float acc = bf[j];
        #pragma unroll 4
        for (int q = 0; q < EMB / 4; q++) {
            float4 w = wr[q], sv = sr[q];
            acc += w.x * sv.x + w.y * sv.y + w.z * sv.z + w.w * sv.w;
        }
        g_film[b * 2 * DM + j] = acc;
    }
}

// ---------------------------------------------------------------------------
// Kernel 2b: split W into bf16 hi/lo
// ---------------------------------------------------------------------------
__global__ void prep_w(const float* __restrict__ W) {
    int i = blockIdx.x * blockDim.x + threadIdx.x;  // over 2*DM*DM/4
    float4 v = ((const float4*)W)[i];
    float e[4] = {v.x, v.y, v.z, v.w};
    ushort4 h4, l4;
    unsigned short* hp = &h4.x;
    unsigned short* lp = &l4.x;
    #pragma unroll
    for (int j = 0; j < 4; j++) {
        __nv_bfloat16 h = __float2bfloat16_rn(e[j]);
        __nv_bfloat16 l = __float2bfloat16_rn(e[j] - __bfloat162float(h));
        hp[j] = __bfloat16_as_ushort(h);
        lp[j] = __bfloat16_as_ushort(l);
    }
    ((ushort4*)g_Wh)[i] = h4;
    ((ushort4*)g_Wl)[i] = l4;
}

// ---------------------------------------------------------------------------
// Kernel 3: S4D complex scan + D-skip + FiLM.
// 16 lanes per d (2 d per warp), each lane 2 f32x2-packed complex pairs
// (4 of 64 states). Block = 128 threads = 8 consecutive d, one batch.
// Writes y2 directly as bf16 hi/lo splits for the tensor-core GEMM.
// ---------------------------------------------------------------------------
__global__ void scan_kernel(const float* __restrict__ A_real,
                            const float* __restrict__ A_imag,
                            const float* __restrict__ Cp,
                            const float* __restrict__ log_dt,
                            const float* __restrict__ B_ssm,
                            const float* __restrict__ D_skip) {
    const int t = threadIdx.x;        // 0..127
    const int grp = t >> 4;           // 0..7  (which d in block)
    const int g = t & 15;             // lane within d-group
    const int gid = blockIdx.x * 8 + grp;
    const int b = gid >> 9;
    const int d = gid & 511;
    const int d0 = (blockIdx.x * 8) & 511;

    const float dt = expf(log_dt[d]);
    unsigned long long Abr[2], Abi[2], nAbi[2], Ccr[2], nCci[2], s_r[2], s_i[2];
    #pragma unroll
    for (int p = 0; p < 2; p++) {
        float abr[2], abi[2], ccr[2], cci[2];
        #pragma unroll
        for (int j = 0; j < 2; j++) {
            int n = g * 4 + p * 2 + j;
            float ar = dt * A_real[d * NS + n];
            float ai = dt * A_imag[d * NS + n];
            float er = expf(ar), sb, cb;
            sincosf(ai, &sb, &cb);
            abr[j] = er * cb;
            abi[j] = er * sb;
            float bs = B_ssm[d * NS + n];
            ccr[j] = Cp[(d * NS + n) * 2 + 0] * bs;
            cci[j] = Cp[(d * NS + n) * 2 + 1] * bs;
        }
        Abr[p]  = pk2(abr[0], abr[1]);
        Abi[p]  = pk2(abi[0], abi[1]);
        nAbi[p] = pk2(-abi[0], -abi[1]);
        Ccr[p]  = pk2(ccr[0], ccr[1]);
        nCci[p] = pk2(-cci[0], -cci[1]);
        s_r[p] = 0ull; s_i[p] = 0ull;
    }
    const float dsk = D_skip[d];
    const float mult  = 1.0f + g_film[b * 2 * DM + d];
    const float shift = g_film[b * 2 * DM + DM + d];

    __shared__ float sx[2][64][8];
    const float* xbase = g_xn + (size_t)b * LSEQ * DM + d0;
    __nv_bfloat16* yh = g_y2h + (size_t)b * LSEQ * DM + d;
    __nv_bfloat16* yl = g_y2l + (size_t)b * LSEQ * DM + d;

    const int ll = t >> 1, half = t & 1;
    *(float4*)&sx[0][ll][half * 4] =
        *(const float4*)(xbase + (size_t)ll * DM + half * 4);
    __syncthreads();

    for (int chunk = 0; chunk < LSEQ / 64; chunk++) {
        const int cur = chunk & 1;
        float4 nld;
        const bool more = (chunk + 1 < LSEQ / 64);
        if (more) {
            nld = *(const float4*)(xbase + (size_t)((chunk + 1) * 64 + ll) * DM + half * 4);
        }
        #pragma unroll 4
        for (int i = 0; i < 64; i++) {
            float xv = sx[cur][i][grp];
            unsigned long long x2 = pk2(xv, xv);
            unsigned long long acc = 0ull;
            #pragma unroll
            for (int p = 0; p < 2; p++) {
                unsigned long long t1 = fma2(nAbi[p], s_i[p], x2);
                unsigned long long nr = fma2(Abr[p], s_r[p], t1);
                unsigned long long u  = mul2(Abi[p], s_r[p]);
                unsigned long long ni = fma2(Abr[p], s_i[p], u);
                s_r[p] = nr; s_i[p] = ni;
                acc = fma2(Ccr[p], nr, acc);
                acc = fma2(nCci[p], ni, acc);
            }
            float2 ac = upk2(acc);
            float tsum = ac.x + ac.y;
            #pragma unroll
            for (int o = 8; o; o >>= 1)
                tsum += __shfl_xor_sync(0xffffffffu, tsum, o);
            if (g == 0) {
                float o = dt * tsum + dsk * xv;
                float v = o * mult + shift;
                __nv_bfloat16 h = __float2bfloat16_rn(v);
                __nv_bfloat16 l = __float2bfloat16_rn(v - __bfloat162float(h));
                size_t idx = (size_t)(chunk * 64 + i) * DM;
                yh[idx] = h;
                yl[idx] = l;
            }
        }
        if (more) {
            *(float4*)&sx[cur ^ 1][ll][half * 4] = nld;
        }
        __syncthreads();
    }
}

// ---------------------------------------------------------------------------
// Kernel 4: out_proj GEMM via 3-pass bf16 split mma.m16n8k16 + GLU + residual.
// Block tile 128m x 64 a-cols (+paired 64 g-cols), BK=32, cp.async 2-stage.
// 8 warps: 4 m x 2 n; warp tile 32m x 32n for both gates.
// ---------------------------------------------------------------------------
#define TBM 128
#define TBK 32
#define ROWW 20                 // padded uint32 words per 32-bf16 row
#define TILEW (128 * ROWW)      // 2560 words per tile buffer

// word offsets inside dynamic smem
#define OFF_AH(st) ((st) * TILEW)
#define OFF_AL(st) (2 * TILEW + (st) * TILEW)
#define OFF_BH(st) (4 * TILEW + (st) * TILEW)
#define OFF_BL(st) (6 * TILEW + (st) * TILEW)
#define SMEM_BYTES (8 * TILEW * 4)

__device__ __forceinline__ void mma_bf16(float d[4], const uint32_t a[4],
                                         const uint32_t b0, const uint32_t b1) {
    asm volatile(
        "mma.sync.aligned.m16n8k16.row.col.f32.bf16.bf16.f32 "
        "{%0,%1,%2,%3}, {%4,%5,%6,%7}, {%8,%9}, {%0,%1,%2,%3};\n"
        : "+f"(d[0]), "+f"(d[1]), "+f"(d[2]), "+f"(d[3])
        : "r"(a[0]), "r"(a[1]), "r"(a[2]), "r"(a[3]), "r"(b0), "r"(b1));
}

__global__ void __launch_bounds__(256, 2)
gemm_glu_tc(const float* __restrict__ bo,
            const float* __restrict__ resid,
            float* __restrict__ out) {
    extern __shared__ uint32_t sm[];
    const uint32_t sbase = (uint32_t)__cvta_generic_to_shared(sm);

    const int tid = threadIdx.x;
    const int m0 = blockIdx.x * TBM;
    const int c0 = blockIdx.y * 64;
    const int warp = tid >> 5, lane = tid & 31;
    const int wm = warp & 3, wn = warp >> 2;
    const int grp = lane >> 2, tig = lane & 3;

    float da[2][4][4];
    float dg[2][4][4];
    #pragma unroll
    for (int mt = 0; mt < 2; mt++)
        #pragma unroll
        for (int nt = 0; nt < 4; nt++)
            #pragma unroll
            for (int r = 0; r < 4; r++) { da[mt][nt][r] = 0.0f; dg[mt][nt][r] = 0.0f; }

    // cp.async mapping: q in [0,512): row=q>>2, 16B chunk ch=q&3 (8 bf16)
    const int r0 = tid >> 2,         ch0 = tid & 3;
    const int r1 = (tid + 256) >> 2, ch1 = tid & 3;
    const int wrow0 = (r0 < 64) ? (c0 + r0) : (DM + c0 + r0 - 64);
    const int wrow1 = (r1 < 64) ? (c0 + r1) : (DM + c0 + r1 - 64);

    auto load_stage = [&](int st, int kt) {
        const __nv_bfloat16* a_h = g_y2h + (size_t)(m0 + r0) * DM + kt + ch0 * 8;
        const __nv_bfloat16* a_h1 = g_y2h + (size_t)(m0 + r1) * DM + kt + ch1 * 8;
        const __nv_bfloat16* a_l = g_y2l + (size_t)(m0 + r0) * DM + kt + ch0 * 8;
        const __nv_bfloat16* a_l1 = g_y2l + (size_t)(m0 + r1) * DM + kt + ch1 * 8;
        const __nv_bfloat16* b_h = g_Wh + (size_t)wrow0 * DM + kt + ch0 * 8;
        const __nv_bfloat16* b_h1 = g_Wh + (size_t)wrow1 * DM + kt + ch1 * 8;
        const __nv_bfloat16* b_l = g_Wl + (size_t)wrow0 * DM + kt + ch0 * 8;
        const __nv_bfloat16* b_l1 = g_Wl + (size_t)wrow1 * DM + kt + ch1 * 8;
        uint32_t d0 = (r0 * ROWW + ch0 * 4) * 4;
        uint32_t d1 = (r1 * ROWW + ch1 * 4) * 4;
        cpa16(sbase + OFF_AH(st) * 4 + d0, a_h);
        cpa16(sbase + OFF_AH(st) * 4 + d1, a_h1);
        cpa16(sbase + OFF_AL(st) * 4 + d0, a_l);
        cpa16(sbase + OFF_AL(st) * 4 + d1, a_l1);
        cpa16(sbase + OFF_BH(st) * 4 + d0, b_h);
        cpa16(sbase + OFF_BH(st) * 4 + d1, b_h1);
        cpa16(sbase + OFF_BL(st) * 4 + d0, b_l);
        cpa16(sbase + OFF_BL(st) * 4 + d1, b_l1);
    };

    load_stage(0, 0);
    asm volatile("cp.async.commit_group;");

    const int NKT = DM / TBK;  // 16
    for (int it = 0; it < NKT; it++) {
        const int cur = it & 1;
        if (it + 1 < NKT) {
            load_stage(cur ^ 1, (it + 1) * TBK);
            asm volatile("cp.async.commit_group;");
            asm volatile("cp.async.wait_group 1;");
        } else {
            asm volatile("cp.async.wait_group 0;");
        }
        __syncthreads();

        const uint32_t* Ah = sm + OFF_AH(cur);
        const uint32_t* Al = sm + OFF_AL(cur);
        const uint32_t* Bh = sm + OFF_BH(cur);
        const uint32_t* Bl = sm + OFF_BL(cur);

        #pragma unroll
        for (int kk = 0; kk < 2; kk++) {
            const int kw = kk * 8;
            uint32_t ah[2][4], al[2][4];
            #pragma unroll
            for (int mt = 0; mt < 2; mt++) {
                int m = wm * 32 + mt * 16;
                int i0 = (m + grp) * ROWW + kw + tig;
                int i1 = (m + grp + 8) * ROWW + kw + tig;
                ah[mt][0] = Ah[i0];     ah[mt][1] = Ah[i1];
                ah[mt][2] = Ah[i0 + 4]; ah[mt][3] = Ah[i1 + 4];
                al[mt][0] = Al[i0];     al[mt][1] = Al[i1];
                al[mt][2] = Al[i0 + 4]; al[mt][3] = Al[i1 + 4];
            }
            // a-gate
            {
                uint32_t bh[4][2], bl[4][2];
                #pragma unroll
                for (int nt = 0; nt < 4; nt++) {
                    int n = wn * 32 + nt * 8 + grp;       // rows 0..63 (a-cols)
                    int ib = n * ROWW + kw + tig;
                    bh[nt][0] = Bh[ib]; bh[nt][1] = Bh[ib + 4];
                    bl[nt][0] = Bl[ib]; bl[nt][1] = Bl[ib + 4];
                }
                #pragma unroll
                for (int mt = 0; mt < 2; mt++)
                    #pragma unroll
                    for (int nt = 0; nt < 4; nt++) {
                        mma_bf16(da[mt][nt], ah[mt], bh[nt][0], bh[nt][1]);
                        mma_bf16(da[mt][nt], ah[mt], bl[nt][0], bl[nt][1]);
                        mma_bf16(da[mt][nt], al[mt], bh[nt][0], bh[nt][1]);
                    }
            }
            // g-gate
            {
                uint32_t bh[4][2], bl[4][2];
                #pragma unroll
                for (int nt = 0; nt < 4; nt++) {
                    int n = 64 + wn * 32 + nt * 8 + grp;  // rows 64..127 (g-cols)
                    int ib = n * ROWW + kw + tig;
                    bh[nt][0] = Bh[ib]; bh[nt][1] = Bh[ib + 4];
                    bl[nt][0] = Bl[ib]; bl[nt][1] = Bl[ib + 4];
                }
                #pragma unroll
                for (int mt = 0; mt < 2; mt++)
                    #pragma unroll
                    for (int nt = 0; nt < 4; nt++) {
                        mma_bf16(dg[mt][nt], ah[mt], bh[nt][0], bh[nt][1]);
                        mma_bf16(dg[mt][nt], ah[mt], bl[nt][0], bl[nt][1]);
                        mma_bf16(dg[mt][nt], al[mt], bh[nt][0], bh[nt][1]);
                    }
            }
        }
        __syncthreads();
    }

    // epilogue: a*sigmoid(g) + residual
    #pragma unroll
    for (int mt = 0; mt < 2; mt++) {
        #pragma unroll
        for (int nt = 0; nt < 4; nt++) {
            int col = c0 + wn * 32 + nt * 8 + tig * 2;
            float ba0 = bo[col], ba1 = bo[col + 1];
            float bg0 = bo[DM + col], bg1 = bo[DM + col + 1];
            #pragma unroll
            for (int half = 0; half < 2; half++) {
                int r = m0 + wm * 32 + mt * 16 + grp + half * 8;
                float a0 = da[mt][nt][half * 2 + 0] + ba0;
                float a1 = da[mt][nt][half * 2 + 1] + ba1;
                float g0 = dg[mt][nt][half * 2 + 0] + bg0;
                float g1 = dg[mt][nt][half * 2 + 1] + bg1;
                float2 res = *(const float2*)(resid + (size_t)r * DM + col);
                float2 o;
                o.x = res.x + a0 * (1.0f / (1.0f + expf(-g0)));
                o.y = res.y + a1 * (1.0f / (1.0f + expf(-g1)));
                *(float2*)(out + (size_t)r * DM + col) = o;
            }
        }
    }
}

// ---------------------------------------------------------------------------
extern "C" void kernel_launch(void* const* d_in, const int* in_sizes, int n_in,
                              void* d_out, int out_size) {
    const float* x      = (const float*)d_in[0];
    const float* emb    = (const float*)d_in[1];
    const float* A_real = (const float*)d_in[2];
    const float* A_imag = (const float*)d_in[3];
    const float* C      = (const float*)d_in[4];
    const float* log_dt = (const float*)d_in[5];
    const float* B_ssm  = (const float*)d_in[6];
    const float* D_skip = (const float*)d_in[7];
    const float* ln_g   = (const float*)d_in[8];
    const float* ln_b   = (const float*)d_in[9];
    const float* W_out  = (const float*)d_in[10];
    const float* b_out  = (const float*)d_in[11];
    const float* W_film = (const float*)d_in[12];
    const float* b_film = (const float*)d_in[13];
    float* out = (float*)d_out;

    static bool configured = false;
    if (!configured) {
        cudaFuncSetAttribute(gemm_glu_tc,
                             cudaFuncAttributeMaxDynamicSharedMemorySize,
                             SMEM_BYTES);
        configured = true;
    }

    ln_kernel<<<BSZ * LSEQ, 128>>>(x, ln_g, ln_b);
    film_kernel<<<BSZ, 256>>>(emb, W_film, b_film);
    prep_w<<<(2 * DM * DM / 4) / 256, 256>>>(W_out);
    scan_kernel<<<(BSZ * DM) / 8, 128>>>(A_real, A_imag, C, log_dt, B_ssm, D_skip);
    gemm_glu_tc<<<dim3((BSZ * LSEQ) / TBM, DM / 64), 256, SMEM_BYTES>>>(b_out, x, out);
}